// round 15
// baseline (speedup 1.0000x reference)
#include <cuda_runtime.h>
#include <math.h>
#include <cfloat>

#define NN 50000
#define NE 800000
#define NG 64
#define AVG_LOG 2.8332133440562162f  /* log(17) */

// ---------------- scratch ----------------
__device__ __align__(16) float d_a[NN * 128];
__device__ __align__(16) float d_b[NN * 128];
__device__ __align__(16) float d_h0[NN * 64];
__device__ __align__(16) float d_h1[NN * 64];
__device__ int   d_deg[NN];
__device__ int   d_rowptr[NN + 1];
__device__ int   d_cursor[NN];
__device__ int   d_csrc[NE];
__device__ float d_ce0[NE];
__device__ float d_ce1[NE];
__device__ float d_wc[256];
__device__ float d_cb[128];
__device__ float d_g[NG * 64];

__device__ const float* g_x;
__device__ const float* g_ea;
__device__ const int*   g_ei;
__device__ int g_ei64;
__device__ int g_b64;

__device__ __forceinline__ int EIV(long i) {
    return g_ei64 ? g_ei[2 * i] : g_ei[i];
}
__device__ __forceinline__ int BV(const int* b, int n) {
    return g_b64 ? b[2 * n] : b[n];
}

// ---------------- probe + zero ----------------
__global__ void k_probe(const void* c0, const void* c1, const void* c2, const int* batch) {
    __shared__ int s_ok[4], s_z[4], s_nz[4];
    const void* cs3[3] = {c0, c1, c2};
    int tid = threadIdx.x;
    int w = tid >> 5, lane = tid & 31;
    if (w < 3) {
        const int* p = (const int*)cs3[w];
        bool ok = true, z = true;
        for (int j = lane; j < 64; j += 32) {
            int v = p[j * 24000 + 13];
            if (v < 0 || v >= NN) ok = false;
            if (p[2 * (j * 12000) + 1] != 0) z = false;
        }
        unsigned bok = __ballot_sync(0xffffffffu, ok);
        unsigned bz = __ballot_sync(0xffffffffu, z);
        if (lane == 0) { s_ok[w] = (bok == 0xffffffffu); s_z[w] = (bz == 0xffffffffu); }
    } else if (w == 3) {
        bool z = true; int nz = 0;
        for (int j = lane; j < 64; j += 32) {
            if (batch[2 * (j * 390) + 1] != 0) z = false;
            if (batch[2 * (j * 390)] != 0) nz++;
        }
        unsigned bz = __ballot_sync(0xffffffffu, z);
        nz += __shfl_xor_sync(0xffffffffu, nz, 16);
        nz += __shfl_xor_sync(0xffffffffu, nz, 8);
        nz += __shfl_xor_sync(0xffffffffu, nz, 4);
        nz += __shfl_xor_sync(0xffffffffu, nz, 2);
        nz += __shfl_xor_sync(0xffffffffu, nz, 1);
        if (lane == 0) { s_z[3] = (bz == 0xffffffffu); s_nz[3] = nz; }
    }
    for (int i = tid; i < NN; i += 1024) d_deg[i] = 0;
    for (int i = tid; i < NG * 64; i += 1024) d_g[i] = 0.f;
    __syncthreads();
    if (tid == 0) {
        int sel = 2;
        if (s_ok[0]) sel = 0;
        else if (s_ok[1]) sel = 1;
        int a = (sel == 0) ? 1 : 0;
        int b = 3 - sel - a;
        g_ei = (const int*)cs3[sel];
        g_x  = (const float*)cs3[a];
        g_ea = (const float*)cs3[b];
        g_ei64 = s_z[sel];
        g_b64 = (s_z[3] && s_nz[3] > 8) ? 1 : 0;
    }
}

__global__ void k_count() {
    int e = blockIdx.x * blockDim.x + threadIdx.x;
    if (e >= NE) return;
    unsigned dn = (unsigned)EIV((long)NE + e);
    if (dn < NN) atomicAdd(&d_deg[dn], 1);
}

// ---------------- coalesced chunked shuffle scan ----------------
__global__ void k_scan() {
    __shared__ int wsums[32];
    __shared__ int carry_s;
    int tid = threadIdx.x;  // 1024
    int lane = tid & 31, w = tid >> 5;
    if (tid == 0) carry_s = 0;
    __syncthreads();
    for (int base = 0; base < NN; base += 1024) {
        int i = base + tid;
        int v = (i < NN) ? d_deg[i] : 0;
        int s = v;
#pragma unroll
        for (int off = 1; off < 32; off <<= 1) {
            int t2 = __shfl_up_sync(0xffffffffu, s, off);
            if (lane >= off) s += t2;
        }
        if (lane == 31) wsums[w] = s;
        __syncthreads();
        if (w == 0) {
            int wv = wsums[lane];
#pragma unroll
            for (int off = 1; off < 32; off <<= 1) {
                int t2 = __shfl_up_sync(0xffffffffu, wv, off);
                if (lane >= off) wv += t2;
            }
            wsums[lane] = wv;
        }
        __syncthreads();
        int excl = carry_s + (w > 0 ? wsums[w - 1] : 0) + s - v;
        if (i < NN) { d_rowptr[i] = excl; d_cursor[i] = excl; }
        __syncthreads();
        if (tid == 0) carry_s += wsums[31];
        __syncthreads();
    }
    if (tid == 0) d_rowptr[NN] = carry_s;
}

__global__ void k_scatter() {
    int e = blockIdx.x * blockDim.x + threadIdx.x;
    if (e >= NE) return;
    unsigned s = (unsigned)EIV(e), dn = (unsigned)EIV((long)NE + e);
    if (dn >= NN || s >= NN) return;
    int p = atomicAdd(&d_cursor[dn], 1);
    d_csrc[p] = (int)s;
    if (g_ei64) {
        d_ce0[p] = g_ea[2 * e];
        d_ce1[p] = g_ea[2 * e + 1];
    } else {
        float2 v = *reinterpret_cast<const float2*>(g_ea + 2 * e);
        d_ce0[p] = v.x;
        d_ce1[p] = v.y;
    }
}

// ---------------- fold edge encoder ----------------
template <int F>
__global__ void k_wc(const float* __restrict__ We, const float* __restrict__ be,
                     const float* __restrict__ Wpre, const float* __restrict__ bpre) {
    int c = blockIdx.x * blockDim.x + threadIdx.x;
    if (c >= 2 * F) return;
    int t = c / F, f = c % F;
    float w0 = 0.f, w1 = 0.f, cb = 0.f;
    for (int k = 0; k < F; k++) {
        float wp = Wpre[((t * 3 + 2) * F + k) * F + f];
        w0 += We[k] * wp;
        w1 += We[F + k] * wp;
        cb += be[k] * wp;
    }
    d_wc[c] = w0;
    d_wc[128 + c] = w1;
    d_cb[c] = cb + bpre[c];
}

// ---------------- proj: tiled GEMM [a|b] = x @ W ----------------
template <int F>
__global__ void k_proj(const float* __restrict__ xin, int useg,
                       const float* __restrict__ Wpre) {
    constexpr int OD = 4 * F;
    constexpr int HALF = OD / 2;
    constexpr int JJ = HALF / 32;
    __shared__ float Ws[F][HALF];
    __shared__ float Xs[32][F + 1];
    const float* xp = useg ? g_x : xin;
    int tid = threadIdx.x;  // 256
    int n0 = blockIdx.x * 32;

    for (int i = tid; i < 32 * F; i += 256) {
        int nb = i / F, k = i % F;
        int n = n0 + nb;
        Xs[nb][k] = (n < NN) ? xp[n * F + k] : 0.f;
    }
    int tcol = tid & 31;
    int trow = tid >> 5;

    for (int half = 0; half < 2; half++) {
        __syncthreads();
        for (int i = tid; i < F * HALF; i += 256) {
            int k = i / HALF, c = i % HALF;
            int gc = half * HALF + c;
            int part = gc / (2 * F);
            int cc = gc - part * 2 * F;
            int t = cc / F, f = cc % F;
            Ws[k][c] = Wpre[((t * 3 + part) * F + k) * F + f];
        }
        __syncthreads();
        float acc[4][JJ];
#pragma unroll
        for (int i = 0; i < 4; i++)
#pragma unroll
            for (int j = 0; j < JJ; j++) acc[i][j] = 0.f;
        for (int k = 0; k < F; k++) {
            float xr[4];
#pragma unroll
            for (int i = 0; i < 4; i++) xr[i] = Xs[trow * 4 + i][k];
#pragma unroll
            for (int j = 0; j < JJ; j++) {
                float w = Ws[k][tcol + 32 * j];
#pragma unroll
                for (int i = 0; i < 4; i++) acc[i][j] = fmaf(xr[i], w, acc[i][j]);
            }
        }
#pragma unroll
        for (int i = 0; i < 4; i++) {
            int n = n0 + trow * 4 + i;
            if (n >= NN) continue;
#pragma unroll
            for (int j = 0; j < JJ; j++) {
                int gc = half * HALF + tcol + 32 * j;
                int part = gc / (2 * F);
                int cc = gc - part * 2 * F;
                if (part) d_b[n * 2 * F + cc] = acc[i][j];
                else      d_a[n * 2 * F + cc] = acc[i][j];
            }
        }
    }
}

// ---------------- agg3: gather + scaled features in smem + k-split GEMM (1 acc set) ----------------
// 8 nodes/block, 256 threads. smem: xs[8][F], fs[2*8][12F], part[8][8][64], Os[8][64].
template <int F>
__global__ void __launch_bounds__(256) k_agg3(
        const float* __restrict__ xin, int useg,
        const float* __restrict__ Wpost, const float* __restrict__ bpost,
        const float* __restrict__ Wlin, const float* __restrict__ blin,
        float* __restrict__ hout) {
    constexpr int TF = 2 * F;
    constexpr int CPL = TF / 32;
    constexpr int FS = 12 * F;           // scaled agg features per (tower,node)
    extern __shared__ float sm[];
    float* xs   = sm;                    // [8][F]
    float* fs   = xs + 8 * F;            // [2*8][FS]
    float* part = fs + 16 * FS;          // [8w][8n][64]
    float* Os   = part + 8 * 8 * 64;     // [8][64]

    int tid = threadIdx.x;
    int warp = tid >> 5, lane = tid & 31;
    int n0 = blockIdx.x * 8;
    const float* xp = useg ? g_x : xin;

    // Phase A: stage x
    for (int i = tid; i < 8 * F; i += 256) {
        int nd = i / F, k = i % F;
        int n = n0 + nd;
        xs[i] = (n < NN) ? xp[n * F + k] : 0.f;
    }

    // Phase B: edge aggregation (warp per node, MLP-4) -> scaled features
    {
        int n = n0 + warp;
        if (n < NN) {
            float wc0[CPL], wc1[CPL], cbv[CPL], aD[CPL];
            float sum[CPL], sq[CPL], mn[CPL], mx[CPL];
#pragma unroll
            for (int i = 0; i < CPL; i++) {
                int c = lane * CPL + i;
                wc0[i] = d_wc[c];
                wc1[i] = d_wc[128 + c];
                cbv[i] = d_cb[c];
                sum[i] = 0.f; sq[i] = 0.f; mn[i] = FLT_MAX; mx[i] = -FLT_MAX;
            }
            {
                const float* ar = d_a + (size_t)n * TF + lane * CPL;
                if (CPL == 4) {
                    float4 v = *reinterpret_cast<const float4*>(ar);
                    aD[0] = v.x; aD[1] = v.y;
                    if (CPL > 2) { aD[CPL - 2] = v.z; aD[CPL - 1] = v.w; }
                } else {
                    float2 v = *reinterpret_cast<const float2*>(ar);
                    aD[0] = v.x; aD[1] = v.y;
                }
            }
            int start = d_rowptr[n], end = d_rowptr[n + 1];
            int cnt = end - start;
            for (int p0 = start; p0 < end; p0 += 32) {
                int p = p0 + lane;
                int sl = 0; float e0l = 0.f, e1l = 0.f;
                if (p < end) { sl = d_csrc[p]; e0l = d_ce0[p]; e1l = d_ce1[p]; }
                int kmax = min(32, end - p0);
                int k = 0;
                for (; k + 4 <= kmax; k += 4) {
                    int src[4]; float e0[4], e1[4];
#pragma unroll
                    for (int q = 0; q < 4; q++) {
                        src[q] = __shfl_sync(0xffffffffu, sl, k + q);
                        e0[q] = __shfl_sync(0xffffffffu, e0l, k + q);
                        e1[q] = __shfl_sync(0xffffffffu, e1l, k + q);
                    }
                    float bv[4][CPL];
#pragma unroll
                    for (int q = 0; q < 4; q++) {
                        const float* br = d_b + (size_t)src[q] * TF + lane * CPL;
                        if (CPL == 4) {
                            float4 v = *reinterpret_cast<const float4*>(br);
                            bv[q][0] = v.x; bv[q][1] = v.y;
                            if (CPL > 2) { bv[q][CPL - 2] = v.z; bv[q][CPL - 1] = v.w; }
                        } else {
                            float2 v = *reinterpret_cast<const float2*>(br);
                            bv[q][0] = v.x; bv[q][1] = v.y;
                        }
                    }
#pragma unroll
                    for (int q = 0; q < 4; q++)
#pragma unroll
                        for (int i = 0; i < CPL; i++) {
                            float m = aD[i] + bv[q][i] + fmaf(e0[q], wc0[i], fmaf(e1[q], wc1[i], cbv[i]));
                            sum[i] += m;
                            sq[i] = fmaf(m, m, sq[i]);
                            mn[i] = fminf(mn[i], m);
                            mx[i] = fmaxf(mx[i], m);
                        }
                }
                for (; k < kmax; k++) {
                    int src = __shfl_sync(0xffffffffu, sl, k);
                    float e0 = __shfl_sync(0xffffffffu, e0l, k);
                    float e1 = __shfl_sync(0xffffffffu, e1l, k);
                    const float* br = d_b + (size_t)src * TF + lane * CPL;
                    float bv[CPL];
                    if (CPL == 4) {
                        float4 v = *reinterpret_cast<const float4*>(br);
                        bv[0] = v.x; bv[1] = v.y;
                        if (CPL > 2) { bv[CPL - 2] = v.z; bv[CPL - 1] = v.w; }
                    } else {
                        float2 v = *reinterpret_cast<const float2*>(br);
                        bv[0] = v.x; bv[1] = v.y;
                    }
#pragma unroll
                    for (int i = 0; i < CPL; i++) {
                        float m = aD[i] + bv[i] + fmaf(e0, wc0[i], fmaf(e1, wc1[i], cbv[i]));
                        sum[i] += m;
                        sq[i] = fmaf(m, m, sq[i]);
                        mn[i] = fminf(mn[i], m);
                        mx[i] = fmaxf(mx[i], m);
                    }
                }
            }
            float dd = (float)max(cnt, 1);
            float inv = 1.f / dd;
            float logd = logf(dd + 1.f);
            float s1 = logd * (1.f / AVG_LOG);
            float s2 = AVG_LOG / logd;
#pragma unroll
            for (int i = 0; i < CPL; i++) {
                int c = lane * CPL + i;
                int t = c / F, f = c % F;
                float mean = sum[i] * inv;
                float var = sq[i] * inv - mean * mean;
                float sd = sqrtf(fmaxf(var, 0.f) + 1e-5f);
                float mnv = cnt ? mn[i] : 0.f;
                float mxv = cnt ? mx[i] : 0.f;
                float* ft = fs + (size_t)(t * 8 + warp) * FS;
                ft[f] = mean;          ft[F + f] = mnv;
                ft[2 * F + f] = mxv;   ft[3 * F + f] = sd;
                ft[4 * F + f] = s1 * mean;        ft[5 * F + f] = s1 * mnv;
                ft[6 * F + f] = s1 * mxv;         ft[7 * F + f] = s1 * sd;
                ft[8 * F + f] = s2 * mean;        ft[9 * F + f] = s2 * mnv;
                ft[10 * F + f] = s2 * mxv;        ft[11 * F + f] = s2 * sd;
            }
        } else {
            for (int t = 0; t < 2; t++) {
                float* ft = fs + (size_t)(t * 8 + warp) * FS;
                for (int i = lane; i < FS; i += 32) ft[i] = 0.f;
            }
        }
    }
    __syncthreads();

    // Phase D: k-split GEMM, single accumulator set.
    {
        int t = lane >> 4;
        int fo = (lane & 15) * 2;
        const float* Wt = Wpost + (size_t)t * 13 * F * 32;
        constexpr int KCH = 13 * F / 8;
        int kk0 = warp * KCH, kk1 = kk0 + KCH;
        float acc[8][2];
#pragma unroll
        for (int nd = 0; nd < 8; nd++) { acc[nd][0] = 0.f; acc[nd][1] = 0.f; }
        int xend = kk1 < F ? kk1 : F;
        for (int kk = kk0; kk < xend; kk++) {
            float2 w = __ldg(reinterpret_cast<const float2*>(Wt + kk * 32 + fo));
#pragma unroll
            for (int nd = 0; nd < 8; nd++) {
                float f = xs[nd * F + kk];
                acc[nd][0] = fmaf(f, w.x, acc[nd][0]);
                acc[nd][1] = fmaf(f, w.y, acc[nd][1]);
            }
        }
        int astart = kk0 > F ? kk0 : F;
        for (int kk = astart; kk < kk1; kk++) {
            float2 w = __ldg(reinterpret_cast<const float2*>(Wt + kk * 32 + fo));
            const float* fb = fs + (size_t)t * 8 * FS + (kk - F);
#pragma unroll
            for (int nd = 0; nd < 8; nd++) {
                float f = fb[nd * FS];
                acc[nd][0] = fmaf(f, w.x, acc[nd][0]);
                acc[nd][1] = fmaf(f, w.y, acc[nd][1]);
            }
        }
        int col = t * 32 + fo;
#pragma unroll
        for (int nd = 0; nd < 8; nd++) {
            int bi = (warp * 8 + nd) * 64 + col;
            part[bi] = acc[nd][0];
            part[bi + 1] = acc[nd][1];
        }
    }
    __syncthreads();

    // Phase E: reduce partials -> Os (+bias)
    for (int idx = tid; idx < 512; idx += 256) {
        int nd = idx >> 6, c = idx & 63;
        float p = __ldg(bpost + c);
#pragma unroll
        for (int w = 0; w < 8; w++) p += part[(w * 8 + nd) * 64 + c];
        Os[idx] = p;
    }
    __syncthreads();

    // Phase F: stage Wlin into part (4096 floats exactly)
    for (int i = tid; i < 4096; i += 256) part[i] = Wlin[i];
    __syncthreads();

    // Phase G: Wlin + relu (warp per node)
    {
        int n = n0 + warp;
        if (n < NN) {
#pragma unroll
            for (int j = 0; j < 2; j++) {
                int c = lane + 32 * j;
                float acc = __ldg(blin + c);
                for (int k = 0; k < 64; k++)
                    acc = fmaf(Os[warp * 64 + k], part[k * 64 + c], acc);
                hout[n * 64 + c] = fmaxf(acc, 0.f);
            }
        }
    }
}

// ---------------- global add pool ----------------
__global__ void k_pool(const int* __restrict__ batch) {
    int t = blockIdx.x * blockDim.x + threadIdx.x;
    if (t >= 64 * 512) return;
    int c = t & 63, slice = t >> 6;
    const int CH = (NN + 511) / 512;
    int n0 = slice * CH, n1 = min(n0 + CH, NN);
    if (n0 >= NN) return;
    float acc = 0.f;
    int bcur = BV(batch, n0);
    for (int n = n0; n < n1; n++) {
        int bn = BV(batch, n);
        if (bn != bcur) {
            if ((unsigned)bcur < NG) atomicAdd(&d_g[bcur * 64 + c], acc);
            acc = 0.f;
            bcur = bn;
        }
        acc += d_h1[n * 64 + c];
    }
    if ((unsigned)bcur < NG) atomicAdd(&d_g[bcur * 64 + c], acc);
}

// ---------------- final MLP ----------------
__global__ void k_final(const float* __restrict__ hls,
                        const float* __restrict__ W1, const float* __restrict__ b1,
                        const float* __restrict__ W2, const float* __restrict__ b2,
                        const float* __restrict__ W3, const float* __restrict__ b3,
                        float* __restrict__ out) {
    __shared__ float bufA[64 * 96];
    __shared__ float bufB[64 * 64];
    int tid = threadIdx.x;
    for (int i = tid; i < 64 * 96; i += 128) {
        int r = i / 96, c = i % 96;
        bufA[i] = (c < 64) ? d_g[r * 64 + c] : __ldg(hls + r * 32 + (c - 64));
    }
    __syncthreads();
    for (int i = tid; i < 64 * 64; i += 128) {
        int r = i / 64, c = i % 64;
        float s = __ldg(b1 + c);
        for (int k = 0; k < 96; k++) s = fmaf(bufA[r * 96 + k], __ldg(W1 + k * 64 + c), s);
        bufB[i] = fmaxf(s, 0.f);
    }
    __syncthreads();
    for (int i = tid; i < 64 * 64; i += 128) {
        int r = i / 64, c = i % 64;
        float s = __ldg(b2 + c);
        for (int k = 0; k < 64; k++) s = fmaf(bufB[r * 64 + k], __ldg(W2 + k * 64 + c), s);
        bufA[i] = fmaxf(s, 0.f);
    }
    __syncthreads();
    for (int i = tid; i < 64; i += 128) {
        float s = __ldg(b3);
        for (int k = 0; k < 64; k++) s = fmaf(bufA[i * 64 + k], __ldg(W3 + k), s);
        out[i] = s;
    }
}

// ---------------- light guard ----------------
__global__ void k_guard(float* out) {
    __shared__ int a1, ag;
    int t = threadIdx.x;  // 256
    if (t == 0) { a1 = 0; ag = 0; }
    __syncthreads();
    bool f1 = false, fg = false;
    for (int j = 0; j < 8; j++) {
        float v = d_h1[(t * 8 + j) * 1560 + 7];
        if (fabsf(v) > 0.f) f1 = true;
    }
    for (int j = t; j < NG * 64; j += 256)
        if (fabsf(d_g[j]) > 0.f) fg = true;
    if (f1) atomicOr(&a1, 1);
    if (fg) atomicOr(&ag, 1);
    __syncthreads();
    if (!a1) { if (t < 64) out[t] = 1e15f; }
    else if (!ag) { if (t < 64) out[t] = 1e24f; }
}

// ---------------- host launch ----------------
extern "C" void kernel_launch(void* const* d_in, const int* in_sizes, int n_in,
                              void* d_out, int out_size) {
    (void)out_size;

    static const int WPAT[22] = {64, 32, 6144, 64, 26624, 64, 4096, 64,
                                 128, 64, 24576, 128, 53248, 64, 4096, 64,
                                 6144, 64, 4096, 64, 64, 1};

    int widx[22];
    int ihls = -1, ibatch = -1;
    int big[3] = {0, 1, 3};
    int nbig = 0;
    int iw0 = -1, scale = 1;
    int nslots = (n_in < 32) ? n_in : 32;

    for (int sc = 1; sc <= 4 && iw0 < 0; sc *= 2) {
        for (int k = 0; k + 22 <= nslots; k++) {
            bool ok = true;
            for (int j = 0; j < 22; j++)
                if (in_sizes[k + j] != WPAT[j] * sc) { ok = false; break; }
            if (ok) { iw0 = k; scale = sc; break; }
        }
    }

    if (iw0 >= 0) {
        for (int j = 0; j < 22; j++) widx[j] = iw0 + j;
        for (int s = 0; s < nslots; s++) {
            if (s >= iw0 && s < iw0 + 22) continue;
            if (in_sizes[s] == 2048 * scale) ihls = s;
            else if (in_sizes[s] >= 1000000 * scale) { if (nbig < 3) big[nbig++] = s; }
            else ibatch = s;
        }
        if (ihls < 0) ihls = 2;
        if (ibatch < 0) ibatch = 4;
        if (nbig == 0) { big[0] = 0; big[1] = 1; big[2] = 3; }
        else if (nbig == 1) { big[1] = big[0]; big[2] = big[0]; }
        else if (nbig == 2) { big[2] = big[1]; }
    } else if (nslots >= 27 && in_sizes[0] == 6144 && in_sizes[14] == NN && in_sizes[25] == 2048) {
        int m[22] = {3, 15, 9, 21, 7, 19, 5, 17, 4, 16, 10, 22, 8, 20, 6, 18, 0, 11, 1, 12, 2, 13};
        for (int j = 0; j < 22; j++) widx[j] = m[j];
        ihls = 25; ibatch = 14;
        big[0] = 26; big[1] = 23; big[2] = 24;
    } else {
        for (int j = 0; j < 22; j++) widx[j] = 5 + j;
        ihls = 2; ibatch = 4;
        big[0] = 0; big[1] = 1; big[2] = 3;
    }

    const float* hls   = (const float*)d_in[ihls];
    const int*   batch = (const int*)d_in[ibatch];

    const float* We0    = (const float*)d_in[widx[0]];
    const float* be0    = (const float*)d_in[widx[1]];
    const float* Wpre0  = (const float*)d_in[widx[2]];
    const float* bpre0  = (const float*)d_in[widx[3]];
    const float* Wpost0 = (const float*)d_in[widx[4]];
    const float* bpost0 = (const float*)d_in[widx[5]];
    const float* Wlin0  = (const float*)d_in[widx[6]];
    const float* blin0  = (const float*)d_in[widx[7]];
    const float* We1    = (const float*)d_in[widx[8]];
    const float* be1    = (const float*)d_in[widx[9]];
    const float* Wpre1  = (const float*)d_in[widx[10]];
    const float* bpre1  = (const float*)d_in[widx[11]];
    const float* Wpost1 = (const float*)d_in[widx[12]];
    const float* bpost1 = (const float*)d_in[widx[13]];
    const float* Wlin1  = (const float*)d_in[widx[14]];
    const float* blin1  = (const float*)d_in[widx[15]];
    const float* W1     = (const float*)d_in[widx[16]];
    const float* b1     = (const float*)d_in[widx[17]];
    const float* W2     = (const float*)d_in[widx[18]];
    const float* b2     = (const float*)d_in[widx[19]];
    const float* W3     = (const float*)d_in[widx[20]];
    const float* b3     = (const float*)d_in[widx[21]];

    float* out = (float*)d_out;

    float *h0p = nullptr, *h1p = nullptr;
    cudaGetSymbolAddress((void**)&h0p, d_h0);
    cudaGetSymbolAddress((void**)&h1p, d_h1);

    // smem: xs 8F + fs 16*12F + part 4096 + Os 512
    const int SM32 = (8 * 32 + 16 * 384 + 4096 + 512) * 4;
    const int SM64 = (8 * 64 + 16 * 768 + 4096 + 512) * 4;
    cudaFuncSetAttribute(k_agg3<32>, cudaFuncAttributeMaxDynamicSharedMemorySize, SM32);
    cudaFuncSetAttribute(k_agg3<64>, cudaFuncAttributeMaxDynamicSharedMemorySize, SM64);

    k_probe<<<1, 1024>>>(d_in[big[0]], d_in[big[1]], d_in[big[2]], batch);
    k_count<<<(NE + 255) / 256, 256>>>();
    k_scan<<<1, 1024>>>();
    k_scatter<<<(NE + 255) / 256, 256>>>();

    // layer 0 (F=32)
    k_wc<32><<<1, 64>>>(We0, be0, Wpre0, bpre0);
    k_proj<32><<<(NN + 31) / 32, 256>>>(nullptr, 1, Wpre0);
    k_agg3<32><<<(NN + 7) / 8, 256, SM32>>>(nullptr, 1, Wpost0, bpost0, Wlin0, blin0, h0p);

    // layer 1 (F=64)
    k_wc<64><<<1, 128>>>(We1, be1, Wpre1, bpre1);
    k_proj<64><<<(NN + 31) / 32, 256>>>(h0p, 0, Wpre1);
    k_agg3<64><<<(NN + 7) / 8, 256, SM64>>>(h0p, 0, Wpost1, bpost1, Wlin1, blin1, h1p);

    // pool + final MLP
    k_pool<<<128, 256>>>(batch);
    k_final<<<1, 128>>>(hls, W1, b1, W2, b2, W3, b3, out);
    k_guard<<<1, 256>>>(out);
}

// round 16
// speedup vs baseline: 1.2115x; 1.2115x over previous
#include <cuda_runtime.h>
#include <math.h>
#include <cfloat>

#define NN 50000
#define NE 800000
#define NG 64
#define AVG_LOG 2.8332133440562162f  /* log(17) */

// packed f32x2 helpers (sm_103a FFMA2 path)
#define PK2(out, f)  asm("mov.b64 %0, {%1, %1};" : "=l"(out) : "f"(f))
#define UPK2(lo, hi, v) asm("mov.b64 {%0, %1}, %2;" : "=f"(lo), "=f"(hi) : "l"(v))
#define FMA2(acc, f2, w2) asm("fma.rn.f32x2 %0, %1, %2, %0;" : "+l"(acc) : "l"(f2), "l"(w2))

// ---------------- scratch ----------------
__device__ __align__(16) float d_a[NN * 128];
__device__ __align__(16) float d_b[NN * 128];
__device__ __align__(16) float d_h0[NN * 64];
__device__ __align__(16) float d_h1[NN * 64];
__device__ int   d_deg[NN];
__device__ int   d_rowptr[NN + 1];
__device__ int   d_cursor[NN];
__device__ int   d_csrc[NE];
__device__ float d_ce0[NE];
__device__ float d_ce1[NE];
__device__ float d_wc[256];
__device__ float d_cb[128];
__device__ float d_g[NG * 64];

__device__ const float* g_x;
__device__ const float* g_ea;
__device__ const int*   g_ei;
__device__ int g_ei64;
__device__ int g_b64;

__device__ __forceinline__ int EIV(long i) {
    return g_ei64 ? g_ei[2 * i] : g_ei[i];
}
__device__ __forceinline__ int BV(const int* b, int n) {
    return g_b64 ? b[2 * n] : b[n];
}

// ---------------- probe + zero ----------------
__global__ void k_probe(const void* c0, const void* c1, const void* c2, const int* batch) {
    __shared__ int s_ok[4], s_z[4], s_nz[4];
    const void* cs3[3] = {c0, c1, c2};
    int tid = threadIdx.x;
    int w = tid >> 5, lane = tid & 31;
    if (w < 3) {
        const int* p = (const int*)cs3[w];
        bool ok = true, z = true;
        for (int j = lane; j < 64; j += 32) {
            int v = p[j * 24000 + 13];
            if (v < 0 || v >= NN) ok = false;
            if (p[2 * (j * 12000) + 1] != 0) z = false;
        }
        unsigned bok = __ballot_sync(0xffffffffu, ok);
        unsigned bz = __ballot_sync(0xffffffffu, z);
        if (lane == 0) { s_ok[w] = (bok == 0xffffffffu); s_z[w] = (bz == 0xffffffffu); }
    } else if (w == 3) {
        bool z = true; int nz = 0;
        for (int j = lane; j < 64; j += 32) {
            if (batch[2 * (j * 390) + 1] != 0) z = false;
            if (batch[2 * (j * 390)] != 0) nz++;
        }
        unsigned bz = __ballot_sync(0xffffffffu, z);
        nz += __shfl_xor_sync(0xffffffffu, nz, 16);
        nz += __shfl_xor_sync(0xffffffffu, nz, 8);
        nz += __shfl_xor_sync(0xffffffffu, nz, 4);
        nz += __shfl_xor_sync(0xffffffffu, nz, 2);
        nz += __shfl_xor_sync(0xffffffffu, nz, 1);
        if (lane == 0) { s_z[3] = (bz == 0xffffffffu); s_nz[3] = nz; }
    }
    for (int i = tid; i < NN; i += 1024) d_deg[i] = 0;
    for (int i = tid; i < NG * 64; i += 1024) d_g[i] = 0.f;
    __syncthreads();
    if (tid == 0) {
        int sel = 2;
        if (s_ok[0]) sel = 0;
        else if (s_ok[1]) sel = 1;
        int a = (sel == 0) ? 1 : 0;
        int b = 3 - sel - a;
        g_ei = (const int*)cs3[sel];
        g_x  = (const float*)cs3[a];
        g_ea = (const float*)cs3[b];
        g_ei64 = s_z[sel];
        g_b64 = (s_z[3] && s_nz[3] > 8) ? 1 : 0;
    }
}

__global__ void k_count() {
    int e = blockIdx.x * blockDim.x + threadIdx.x;
    if (e >= NE) return;
    unsigned dn = (unsigned)EIV((long)NE + e);
    if (dn < NN) atomicAdd(&d_deg[dn], 1);
}

// ---------------- coalesced chunked shuffle scan ----------------
__global__ void k_scan() {
    __shared__ int wsums[32];
    __shared__ int carry_s;
    int tid = threadIdx.x;  // 1024
    int lane = tid & 31, w = tid >> 5;
    if (tid == 0) carry_s = 0;
    __syncthreads();
    for (int base = 0; base < NN; base += 1024) {
        int i = base + tid;
        int v = (i < NN) ? d_deg[i] : 0;
        int s = v;
#pragma unroll
        for (int off = 1; off < 32; off <<= 1) {
            int t2 = __shfl_up_sync(0xffffffffu, s, off);
            if (lane >= off) s += t2;
        }
        if (lane == 31) wsums[w] = s;
        __syncthreads();
        if (w == 0) {
            int wv = wsums[lane];
#pragma unroll
            for (int off = 1; off < 32; off <<= 1) {
                int t2 = __shfl_up_sync(0xffffffffu, wv, off);
                if (lane >= off) wv += t2;
            }
            wsums[lane] = wv;
        }
        __syncthreads();
        int excl = carry_s + (w > 0 ? wsums[w - 1] : 0) + s - v;
        if (i < NN) { d_rowptr[i] = excl; d_cursor[i] = excl; }
        __syncthreads();
        if (tid == 0) carry_s += wsums[31];
        __syncthreads();
    }
    if (tid == 0) d_rowptr[NN] = carry_s;
}

__global__ void k_scatter() {
    int e = blockIdx.x * blockDim.x + threadIdx.x;
    if (e >= NE) return;
    unsigned s = (unsigned)EIV(e), dn = (unsigned)EIV((long)NE + e);
    if (dn >= NN || s >= NN) return;
    int p = atomicAdd(&d_cursor[dn], 1);
    d_csrc[p] = (int)s;
    if (g_ei64) {
        d_ce0[p] = g_ea[2 * e];
        d_ce1[p] = g_ea[2 * e + 1];
    } else {
        float2 v = *reinterpret_cast<const float2*>(g_ea + 2 * e);
        d_ce0[p] = v.x;
        d_ce1[p] = v.y;
    }
}

// ---------------- fold edge encoder ----------------
template <int F>
__global__ void k_wc(const float* __restrict__ We, const float* __restrict__ be,
                     const float* __restrict__ Wpre, const float* __restrict__ bpre) {
    int c = blockIdx.x * blockDim.x + threadIdx.x;
    if (c >= 2 * F) return;
    int t = c / F, f = c % F;
    float w0 = 0.f, w1 = 0.f, cb = 0.f;
    for (int k = 0; k < F; k++) {
        float wp = Wpre[((t * 3 + 2) * F + k) * F + f];
        w0 += We[k] * wp;
        w1 += We[F + k] * wp;
        cb += be[k] * wp;
    }
    d_wc[c] = w0;
    d_wc[128 + c] = w1;
    d_cb[c] = cb + bpre[c];
}

// ---------------- proj: tiled GEMM [a|b] = x @ W ----------------
template <int F>
__global__ void k_proj(const float* __restrict__ xin, int useg,
                       const float* __restrict__ Wpre) {
    constexpr int OD = 4 * F;
    constexpr int HALF = OD / 2;
    constexpr int JJ = HALF / 32;
    __shared__ float Ws[F][HALF];
    __shared__ float Xs[32][F + 1];
    const float* xp = useg ? g_x : xin;
    int tid = threadIdx.x;  // 256
    int n0 = blockIdx.x * 32;

    for (int i = tid; i < 32 * F; i += 256) {
        int nb = i / F, k = i % F;
        int n = n0 + nb;
        Xs[nb][k] = (n < NN) ? xp[n * F + k] : 0.f;
    }
    int tcol = tid & 31;
    int trow = tid >> 5;

    for (int half = 0; half < 2; half++) {
        __syncthreads();
        for (int i = tid; i < F * HALF; i += 256) {
            int k = i / HALF, c = i % HALF;
            int gc = half * HALF + c;
            int part = gc / (2 * F);
            int cc = gc - part * 2 * F;
            int t = cc / F, f = cc % F;
            Ws[k][c] = Wpre[((t * 3 + part) * F + k) * F + f];
        }
        __syncthreads();
        float acc[4][JJ];
#pragma unroll
        for (int i = 0; i < 4; i++)
#pragma unroll
            for (int j = 0; j < JJ; j++) acc[i][j] = 0.f;
        for (int k = 0; k < F; k++) {
            float xr[4];
#pragma unroll
            for (int i = 0; i < 4; i++) xr[i] = Xs[trow * 4 + i][k];
#pragma unroll
            for (int j = 0; j < JJ; j++) {
                float w = Ws[k][tcol + 32 * j];
#pragma unroll
                for (int i = 0; i < 4; i++) acc[i][j] = fmaf(xr[i], w, acc[i][j]);
            }
        }
#pragma unroll
        for (int i = 0; i < 4; i++) {
            int n = n0 + trow * 4 + i;
            if (n >= NN) continue;
#pragma unroll
            for (int j = 0; j < JJ; j++) {
                int gc = half * HALF + tcol + 32 * j;
                int part = gc / (2 * F);
                int cc = gc - part * 2 * F;
                if (part) d_b[n * 2 * F + cc] = acc[i][j];
                else      d_a[n * 2 * F + cc] = acc[i][j];
            }
        }
    }
}

// ---------------- agg2: gather (warp/node) + k-split post GEMM (f32x2) + reduce + Wlin ----------------
// 8 nodes/block, 256 threads.
template <int F>
__global__ void __launch_bounds__(256) k_agg2(
        const float* __restrict__ xin, int useg,
        const float* __restrict__ Wpost, const float* __restrict__ bpost,
        const float* __restrict__ Wlin, const float* __restrict__ blin,
        float* __restrict__ hout) {
    constexpr int TF = 2 * F;
    constexpr int CPL = TF / 32;
    constexpr int NAGG = 8 * F;          // per-node agg floats (2 towers x 4F)
    extern __shared__ float sm[];
    float* As   = sm;                    // [8][NAGG]
    float* xs   = As + 8 * NAGG;         // [8][F]
    float* part = xs + 8 * F;            // [3][8w][8n][64]
    float* Os   = part + 3 * 8 * 8 * 64; // [8][64]
    float* s1s  = Os + 8 * 64;           // [8]
    float* s2s  = s1s + 8;               // [8]

    int tid = threadIdx.x;
    int warp = tid >> 5, lane = tid & 31;
    int n0 = blockIdx.x * 8;
    const float* xp = useg ? g_x : xin;

    // Phase A: stage x + scalers
    for (int i = tid; i < 8 * F; i += 256) {
        int nd = i / F, k = i % F;
        int n = n0 + nd;
        xs[i] = (n < NN) ? xp[n * F + k] : 0.f;
    }
    if (tid < 8) {
        int n = n0 + tid;
        int cnt = (n < NN) ? d_rowptr[n + 1] - d_rowptr[n] : 0;
        float dd = (float)max(cnt, 1);
        float logd = logf(dd + 1.f);
        s1s[tid] = logd * (1.f / AVG_LOG);
        s2s[tid] = AVG_LOG / logd;
    }

    // Phase B: edge aggregation (warp per node, MLP-4)
    {
        int n = n0 + warp;
        if (n < NN) {
            float wc0[CPL], wc1[CPL], cbv[CPL], aD[CPL];
            float sum[CPL], sq[CPL], mn[CPL], mx[CPL];
#pragma unroll
            for (int i = 0; i < CPL; i++) {
                int c = lane * CPL + i;
                wc0[i] = d_wc[c];
                wc1[i] = d_wc[128 + c];
                cbv[i] = d_cb[c];
                sum[i] = 0.f; sq[i] = 0.f; mn[i] = FLT_MAX; mx[i] = -FLT_MAX;
            }
            {
                const float* ar = d_a + (size_t)n * TF + lane * CPL;
                if (CPL == 4) {
                    float4 v = *reinterpret_cast<const float4*>(ar);
                    aD[0] = v.x; aD[1] = v.y;
                    if (CPL > 2) { aD[CPL - 2] = v.z; aD[CPL - 1] = v.w; }
                } else {
                    float2 v = *reinterpret_cast<const float2*>(ar);
                    aD[0] = v.x; aD[1] = v.y;
                }
            }
            int start = d_rowptr[n], end = d_rowptr[n + 1];
            int cnt = end - start;
            for (int p0 = start; p0 < end; p0 += 32) {
                int p = p0 + lane;
                int sl = 0; float e0l = 0.f, e1l = 0.f;
                if (p < end) { sl = d_csrc[p]; e0l = d_ce0[p]; e1l = d_ce1[p]; }
                int kmax = min(32, end - p0);
                int k = 0;
                for (; k + 4 <= kmax; k += 4) {
                    int src[4]; float e0[4], e1[4];
#pragma unroll
                    for (int q = 0; q < 4; q++) {
                        src[q] = __shfl_sync(0xffffffffu, sl, k + q);
                        e0[q] = __shfl_sync(0xffffffffu, e0l, k + q);
                        e1[q] = __shfl_sync(0xffffffffu, e1l, k + q);
                    }
                    float bv[4][CPL];
#pragma unroll
                    for (int q = 0; q < 4; q++) {
                        const float* br = d_b + (size_t)src[q] * TF + lane * CPL;
                        if (CPL == 4) {
                            float4 v = *reinterpret_cast<const float4*>(br);
                            bv[q][0] = v.x; bv[q][1] = v.y;
                            if (CPL > 2) { bv[q][CPL - 2] = v.z; bv[q][CPL - 1] = v.w; }
                        } else {
                            float2 v = *reinterpret_cast<const float2*>(br);
                            bv[q][0] = v.x; bv[q][1] = v.y;
                        }
                    }
#pragma unroll
                    for (int q = 0; q < 4; q++)
#pragma unroll
                        for (int i = 0; i < CPL; i++) {
                            float m = aD[i] + bv[q][i] + fmaf(e0[q], wc0[i], fmaf(e1[q], wc1[i], cbv[i]));
                            sum[i] += m;
                            sq[i] = fmaf(m, m, sq[i]);
                            mn[i] = fminf(mn[i], m);
                            mx[i] = fmaxf(mx[i], m);
                        }
                }
                for (; k < kmax; k++) {
                    int src = __shfl_sync(0xffffffffu, sl, k);
                    float e0 = __shfl_sync(0xffffffffu, e0l, k);
                    float e1 = __shfl_sync(0xffffffffu, e1l, k);
                    const float* br = d_b + (size_t)src * TF + lane * CPL;
                    float bv[CPL];
                    if (CPL == 4) {
                        float4 v = *reinterpret_cast<const float4*>(br);
                        bv[0] = v.x; bv[1] = v.y;
                        if (CPL > 2) { bv[CPL - 2] = v.z; bv[CPL - 1] = v.w; }
                    } else {
                        float2 v = *reinterpret_cast<const float2*>(br);
                        bv[0] = v.x; bv[1] = v.y;
                    }
#pragma unroll
                    for (int i = 0; i < CPL; i++) {
                        float m = aD[i] + bv[i] + fmaf(e0, wc0[i], fmaf(e1, wc1[i], cbv[i]));
                        sum[i] += m;
                        sq[i] = fmaf(m, m, sq[i]);
                        mn[i] = fminf(mn[i], m);
                        mx[i] = fmaxf(mx[i], m);
                    }
                }
            }
            float dd = (float)max(cnt, 1);
            float inv = 1.f / dd;
            float* base = As + warp * NAGG;
#pragma unroll
            for (int i = 0; i < CPL; i++) {
                int c = lane * CPL + i;
                int t = c / F, f = c % F;
                float mean = sum[i] * inv;
                float var = sq[i] * inv - mean * mean;
                float sd = sqrtf(fmaxf(var, 0.f) + 1e-5f);
                float* bt = base + t * 4 * F;
                bt[f] = mean;
                bt[F + f] = cnt ? mn[i] : 0.f;
                bt[2 * F + f] = cnt ? mx[i] : 0.f;
                bt[3 * F + f] = sd;
            }
        } else {
            float* base = As + warp * NAGG;
            for (int i = lane; i < NAGG; i += 32) base[i] = 0.f;
        }
    }
    __syncthreads();

    // Phase D: k-split partial GEMM with packed f32x2 FMAs.
    {
        int t = lane >> 4;
        int fo = (lane & 15) * 2;
        const float* Wt = Wpost + (size_t)t * 13 * F * 32;
        unsigned long long a1[8], a2[8], a3[8];
#pragma unroll
        for (int nd = 0; nd < 8; nd++) { a1[nd] = 0ull; a2[nd] = 0ull; a3[nd] = 0ull; }

        // x part: k in [warp*F/8, ...)
        constexpr int XCH = F / 8;
        int kx0 = warp * XCH;
#pragma unroll
        for (int kq = 0; kq < XCH; kq++) {
            int kk = kx0 + kq;
            unsigned long long w = *reinterpret_cast<const unsigned long long*>(Wt + kk * 32 + fo);
#pragma unroll
            for (int nd = 0; nd < 8; nd++) {
                unsigned long long fp;
                PK2(fp, xs[nd * F + kk]);
                FMA2(a1[nd], fp, w);
            }
        }
        // agg part: ka in [warp*F/2, ...), spans [0,4F) across 8 warps
        constexpr int ACH = F / 2;
        int ka0 = warp * ACH;
#pragma unroll 4
        for (int kq = 0; kq < ACH; kq++) {
            int ka = ka0 + kq;
            unsigned long long wa = *reinterpret_cast<const unsigned long long*>(Wt + (F + ka) * 32 + fo);
            unsigned long long wb = *reinterpret_cast<const unsigned long long*>(Wt + (5 * F + ka) * 32 + fo);
            unsigned long long wc = *reinterpret_cast<const unsigned long long*>(Wt + (9 * F + ka) * 32 + fo);
#pragma unroll
            for (int nd = 0; nd < 8; nd++) {
                unsigned long long fp;
                PK2(fp, As[nd * NAGG + t * 4 * F + ka]);
                FMA2(a1[nd], fp, wa);
                FMA2(a2[nd], fp, wb);
                FMA2(a3[nd], fp, wc);
            }
        }
        // write partials: part[set][warp][node][col]
        int col = t * 32 + fo;
#pragma unroll
        for (int nd = 0; nd < 8; nd++) {
            int bi = (warp * 8 + nd) * 64 + col;
            float lo, hi;
            UPK2(lo, hi, a1[nd]); part[bi] = lo;        part[bi + 1] = hi;
            UPK2(lo, hi, a2[nd]); part[4096 + bi] = lo; part[4096 + bi + 1] = hi;
            UPK2(lo, hi, a3[nd]); part[8192 + bi] = lo; part[8192 + bi + 1] = hi;
        }
    }
    __syncthreads();

    // Phase E: reduce partials -> Os
    for (int idx = tid; idx < 512; idx += 256) {
        int nd = idx >> 6, c = idx & 63;
        float p1 = 0.f, p2 = 0.f, p3 = 0.f;
#pragma unroll
        for (int w = 0; w < 8; w++) {
            int bi = (w * 8 + nd) * 64 + c;
            p1 += part[bi];
            p2 += part[4096 + bi];
            p3 += part[8192 + bi];
        }
        Os[idx] = __ldg(bpost + c) + p1 + s1s[nd] * p2 + s2s[nd] * p3;
    }
    __syncthreads();

    // Phase F: stage Wlin into part space
    for (int i = tid; i < 4096; i += 256) part[i] = Wlin[i];
    __syncthreads();

    // Phase G: Wlin + relu (warp per node)
    {
        int n = n0 + warp;
        if (n < NN) {
#pragma unroll
            for (int j = 0; j < 2; j++) {
                int c = lane + 32 * j;
                float acc = __ldg(blin + c);
                for (int k = 0; k < 64; k++)
                    acc = fmaf(Os[warp * 64 + k], part[k * 64 + c], acc);
                hout[n * 64 + c] = fmaxf(acc, 0.f);
            }
        }
    }
}

// ---------------- global add pool ----------------
__global__ void k_pool(const int* __restrict__ batch) {
    int t = blockIdx.x * blockDim.x + threadIdx.x;
    if (t >= 64 * 512) return;
    int c = t & 63, slice = t >> 6;
    const int CH = (NN + 511) / 512;
    int n0 = slice * CH, n1 = min(n0 + CH, NN);
    if (n0 >= NN) return;
    float acc = 0.f;
    int bcur = BV(batch, n0);
    for (int n = n0; n < n1; n++) {
        int bn = BV(batch, n);
        if (bn != bcur) {
            if ((unsigned)bcur < NG) atomicAdd(&d_g[bcur * 64 + c], acc);
            acc = 0.f;
            bcur = bn;
        }
        acc += d_h1[n * 64 + c];
    }
    if ((unsigned)bcur < NG) atomicAdd(&d_g[bcur * 64 + c], acc);
}

// ---------------- final MLP ----------------
__global__ void k_final(const float* __restrict__ hls,
                        const float* __restrict__ W1, const float* __restrict__ b1,
                        const float* __restrict__ W2, const float* __restrict__ b2,
                        const float* __restrict__ W3, const float* __restrict__ b3,
                        float* __restrict__ out) {
    __shared__ float bufA[64 * 96];
    __shared__ float bufB[64 * 64];
    int tid = threadIdx.x;
    for (int i = tid; i < 64 * 96; i += 128) {
        int r = i / 96, c = i % 96;
        bufA[i] = (c < 64) ? d_g[r * 64 + c] : __ldg(hls + r * 32 + (c - 64));
    }
    __syncthreads();
    for (int i = tid; i < 64 * 64; i += 128) {
        int r = i / 64, c = i % 64;
        float s = __ldg(b1 + c);
        for (int k = 0; k < 96; k++) s = fmaf(bufA[r * 96 + k], __ldg(W1 + k * 64 + c), s);
        bufB[i] = fmaxf(s, 0.f);
    }
    __syncthreads();
    for (int i = tid; i < 64 * 64; i += 128) {
        int r = i / 64, c = i % 64;
        float s = __ldg(b2 + c);
        for (int k = 0; k < 64; k++) s = fmaf(bufB[r * 64 + k], __ldg(W2 + k * 64 + c), s);
        bufA[i] = fmaxf(s, 0.f);
    }
    __syncthreads();
    for (int i = tid; i < 64; i += 128) {
        float s = __ldg(b3);
        for (int k = 0; k < 64; k++) s = fmaf(bufA[i * 64 + k], __ldg(W3 + k), s);
        out[i] = s;
    }
}

// ---------------- light guard ----------------
__global__ void k_guard(float* out) {
    __shared__ int a1, ag;
    int t = threadIdx.x;  // 256
    if (t == 0) { a1 = 0; ag = 0; }
    __syncthreads();
    bool f1 = false, fg = false;
    for (int j = 0; j < 8; j++) {
        float v = d_h1[(t * 8 + j) * 1560 + 7];
        if (fabsf(v) > 0.f) f1 = true;
    }
    for (int j = t; j < NG * 64; j += 256)
        if (fabsf(d_g[j]) > 0.f) fg = true;
    if (f1) atomicOr(&a1, 1);
    if (fg) atomicOr(&ag, 1);
    __syncthreads();
    if (!a1) { if (t < 64) out[t] = 1e15f; }
    else if (!ag) { if (t < 64) out[t] = 1e24f; }
}

// ---------------- host launch ----------------
extern "C" void kernel_launch(void* const* d_in, const int* in_sizes, int n_in,
                              void* d_out, int out_size) {
    (void)out_size;

    static const int WPAT[22] = {64, 32, 6144, 64, 26624, 64, 4096, 64,
                                 128, 64, 24576, 128, 53248, 64, 4096, 64,
                                 6144, 64, 4096, 64, 64, 1};

    int widx[22];
    int ihls = -1, ibatch = -1;
    int big[3] = {0, 1, 3};
    int nbig = 0;
    int iw0 = -1, scale = 1;
    int nslots = (n_in < 32) ? n_in : 32;

    for (int sc = 1; sc <= 4 && iw0 < 0; sc *= 2) {
        for (int k = 0; k + 22 <= nslots; k++) {
            bool ok = true;
            for (int j = 0; j < 22; j++)
                if (in_sizes[k + j] != WPAT[j] * sc) { ok = false; break; }
            if (ok) { iw0 = k; scale = sc; break; }
        }
    }

    if (iw0 >= 0) {
        for (int j = 0; j < 22; j++) widx[j] = iw0 + j;
        for (int s = 0; s < nslots; s++) {
            if (s >= iw0 && s < iw0 + 22) continue;
            if (in_sizes[s] == 2048 * scale) ihls = s;
            else if (in_sizes[s] >= 1000000 * scale) { if (nbig < 3) big[nbig++] = s; }
            else ibatch = s;
        }
        if (ihls < 0) ihls = 2;
        if (ibatch < 0) ibatch = 4;
        if (nbig == 0) { big[0] = 0; big[1] = 1; big[2] = 3; }
        else if (nbig == 1) { big[1] = big[0]; big[2] = big[0]; }
        else if (nbig == 2) { big[2] = big[1]; }
    } else if (nslots >= 27 && in_sizes[0] == 6144 && in_sizes[14] == NN && in_sizes[25] == 2048) {
        int m[22] = {3, 15, 9, 21, 7, 19, 5, 17, 4, 16, 10, 22, 8, 20, 6, 18, 0, 11, 1, 12, 2, 13};
        for (int j = 0; j < 22; j++) widx[j] = m[j];
        ihls = 25; ibatch = 14;
        big[0] = 26; big[1] = 23; big[2] = 24;
    } else {
        for (int j = 0; j < 22; j++) widx[j] = 5 + j;
        ihls = 2; ibatch = 4;
        big[0] = 0; big[1] = 1; big[2] = 3;
    }

    const float* hls   = (const float*)d_in[ihls];
    const int*   batch = (const int*)d_in[ibatch];

    const float* We0    = (const float*)d_in[widx[0]];
    const float* be0    = (const float*)d_in[widx[1]];
    const float* Wpre0  = (const float*)d_in[widx[2]];
    const float* bpre0  = (const float*)d_in[widx[3]];
    const float* Wpost0 = (const float*)d_in[widx[4]];
    const float* bpost0 = (const float*)d_in[widx[5]];
    const float* Wlin0  = (const float*)d_in[widx[6]];
    const float* blin0  = (const float*)d_in[widx[7]];
    const float* We1    = (const float*)d_in[widx[8]];
    const float* be1    = (const float*)d_in[widx[9]];
    const float* Wpre1  = (const float*)d_in[widx[10]];
    const float* bpre1  = (const float*)d_in[widx[11]];
    const float* Wpost1 = (const float*)d_in[widx[12]];
    const float* bpost1 = (const float*)d_in[widx[13]];
    const float* Wlin1  = (const float*)d_in[widx[14]];
    const float* blin1  = (const float*)d_in[widx[15]];
    const float* W1     = (const float*)d_in[widx[16]];
    const float* b1     = (const float*)d_in[widx[17]];
    const float* W2     = (const float*)d_in[widx[18]];
    const float* b2     = (const float*)d_in[widx[19]];
    const float* W3     = (const float*)d_in[widx[20]];
    const float* b3     = (const float*)d_in[widx[21]];

    float* out = (float*)d_out;

    float *h0p = nullptr, *h1p = nullptr;
    cudaGetSymbolAddress((void**)&h0p, d_h0);
    cudaGetSymbolAddress((void**)&h1p, d_h1);

    // smem: As 8*8F + xs 8*F + part 12288 + Os 512 + 16
    const int SM32 = (8 * 256 + 8 * 32 + 12288 + 512 + 16) * 4;
    const int SM64 = (8 * 512 + 8 * 64 + 12288 + 512 + 16) * 4;
    cudaFuncSetAttribute(k_agg2<32>, cudaFuncAttributeMaxDynamicSharedMemorySize, SM32);
    cudaFuncSetAttribute(k_agg2<64>, cudaFuncAttributeMaxDynamicSharedMemorySize, SM64);

    k_probe<<<1, 1024>>>(d_in[big[0]], d_in[big[1]], d_in[big[2]], batch);
    k_count<<<(NE + 255) / 256, 256>>>();
    k_scan<<<1, 1024>>>();
    k_scatter<<<(NE + 255) / 256, 256>>>();

    // layer 0 (F=32)
    k_wc<32><<<1, 64>>>(We0, be0, Wpre0, bpre0);
    k_proj<32><<<(NN + 31) / 32, 256>>>(nullptr, 1, Wpre0);
    k_agg2<32><<<(NN + 7) / 8, 256, SM32>>>(nullptr, 1, Wpost0, bpost0, Wlin0, blin0, h0p);

    // layer 1 (F=64)
    k_wc<64><<<1, 128>>>(We1, be1, Wpre1, bpre1);
    k_proj<64><<<(NN + 31) / 32, 256>>>(h0p, 0, Wpre1);
    k_agg2<64><<<(NN + 7) / 8, 256, SM64>>>(h0p, 0, Wpost1, bpost1, Wlin1, blin1, h1p);

    // pool + final MLP
    k_pool<<<128, 256>>>(batch);
    k_final<<<1, 128>>>(hls, W1, b1, W2, b2, W3, b3, out);
    k_guard<<<1, 256>>>(out);
}